// round 3
// baseline (speedup 1.0000x reference)
#include <cuda_runtime.h>
#include <math.h>

#define B_TOTAL 32768
#define X_DIM   30
#define Y_DIM   30
#define F_DIM   6
#define CELLS   (X_DIM * Y_DIM)        // 900
#define GRID    128
#define THREADS 256
#define PRE_BLOCKS 113                  // 112 blocks x 8 cells + 1 block x 4 cells

__device__ float    g_S[CELLS];
__device__ unsigned g_ctr  = 0;   // precompute-done counter
__device__ unsigned g_done = 0;   // block-completion counter (for reset)

__global__ void __launch_bounds__(THREADS)
fused_kernel(const float* __restrict__ phi,
             const float* __restrict__ succ,
             const float* __restrict__ w,
             float* __restrict__ out) {
    const int tid = threadIdx.x;
    const int bid = blockIdx.x;

    // ---- Issue batch-data loads FIRST so DRAM latency overlaps precompute ----
    const int b = bid * THREADS + tid;
    const float4* ph = (const float4*)(phi + (size_t)b * 20);
    const float4 a0 = ph[0];
    const float4 a1 = ph[1];
    const float4 a2 = ph[2];
    const float4 a3 = ph[3];
    const float4 a4 = ph[4];

    const float w0 = __ldg(&w[0]), w1 = __ldg(&w[1]), w2 = __ldg(&w[2]);
    const float w3 = __ldg(&w[3]), w4 = __ldg(&w[4]), w5 = __ldg(&w[5]);

    // ---- Producer phase: blocks 0..112 compute S for 8 cells each ----
    // tid = h*128 + p ; h in {0,1} selects a 4-cell group, p = policy index.
    __shared__ float smax[2][4][4];
    __shared__ float ssum[2][4][4][2];

    if (bid < PRE_BLOCKS) {
        const int h    = tid >> 7;
        const int p    = tid & 127;
        const int lane = tid & 31;
        const int w4g  = (tid >> 5) & 3;      // warp within h-group
        const int cell0 = bid * 8 + h * 4;
        const bool valid = cell0 < CELLS;     // block 112, h=1 is out of range

        float v[4], x[4];
        if (valid) {
            // byte offset = p*21600 + cell0*24 ; cell0 = 8*bid+4h -> 192*bid + 96*h : 16B-aligned
            const float4* base =
                (const float4*)(succ + (size_t)p * (CELLS * F_DIM) + (size_t)cell0 * F_DIM);
            const float4 q0 = base[0], q1 = base[1], q2 = base[2];
            const float4 q3 = base[3], q4 = base[4], q5 = base[5];

            v[0] = q0.x*w0 + q0.y*w1 + q0.z*w2 + q0.w*w3 + q1.x*w4 + q1.y*w5;
            v[1] = q1.z*w0 + q1.w*w1 + q2.x*w2 + q2.y*w3 + q2.z*w4 + q2.w*w5;
            v[2] = q3.x*w0 + q3.y*w1 + q3.z*w2 + q3.w*w3 + q4.x*w4 + q4.y*w5;
            v[3] = q4.z*w0 + q4.w*w1 + q5.x*w2 + q5.y*w3 + q5.z*w4 + q5.w*w5;

#pragma unroll
            for (int j = 0; j < 4; ++j) x[j] = v[j] / 0.001f;   // match vs / T

#pragma unroll
            for (int j = 0; j < 4; ++j) {
                float mm = x[j];
#pragma unroll
                for (int s = 16; s > 0; s >>= 1)
                    mm = fmaxf(mm, __shfl_xor_sync(0xFFFFFFFFu, mm, s));
                if (lane == 0) smax[h][j][w4g] = mm;
            }
        }
        __syncthreads();

        if (valid) {
#pragma unroll
            for (int j = 0; j < 4; ++j) {
                const float mx = fmaxf(fmaxf(smax[h][j][0], smax[h][j][1]),
                                       fmaxf(smax[h][j][2], smax[h][j][3]));
                float e  = expf(x[j] - mx);
                float ev = e * v[j];
#pragma unroll
                for (int s = 16; s > 0; s >>= 1) {
                    e  += __shfl_xor_sync(0xFFFFFFFFu, e,  s);
                    ev += __shfl_xor_sync(0xFFFFFFFFu, ev, s);
                }
                if (lane == 0) { ssum[h][j][w4g][0] = e; ssum[h][j][w4g][1] = ev; }
            }
        }
        __syncthreads();

        if (valid && (tid & 127) < 4) {
            const int h2 = tid >> 7;
            const int j  = tid & 3;
            const float se  = ssum[h2][j][0][0] + ssum[h2][j][1][0]
                            + ssum[h2][j][2][0] + ssum[h2][j][3][0];
            const float sev = ssum[h2][j][0][1] + ssum[h2][j][1][1]
                            + ssum[h2][j][2][1] + ssum[h2][j][3][1];
            g_S[cell0 + j] = sev / se;
        }
        __threadfence();
        __syncthreads();
        if (tid == 0) atomicAdd(&g_ctr, 1u);
    }

    // ---- Wait until all S entries are published ----
    if (tid == 0) {
        while (atomicAdd(&g_ctr, 0u) < PRE_BLOCKS) __nanosleep(32);
    }
    __syncthreads();

    // ---- Consumer phase: every thread finishes one batch element ----
    const float pr0 = a0.x*w0 + a0.y*w1 + a0.z*w2 + a0.w*w3 + a1.x*w4 + a1.y*w5;
    const float pr1 = a2.z*w0 + a2.w*w1 + a3.x*w2 + a3.y*w3 + a3.z*w4 + a3.w*w5;

    const int is0 = (int)a1.z * Y_DIM + (int)a1.w;
    const int ie0 = (int)a2.x * Y_DIM + (int)a2.y;
    const int is1 = (int)a4.x * Y_DIM + (int)a4.y;
    const int ie1 = (int)a4.z * Y_DIM + (int)a4.w;

    const float d0 = pr0 + (__ldcg(&g_S[ie0]) - __ldcg(&g_S[is0]));
    const float d1 = pr1 + (__ldcg(&g_S[ie1]) - __ldcg(&g_S[is1]));

    const float diff = d0 - d1;
    float2 r;
    r.x = 1.0f / (1.0f + expf(-diff));
    r.y = 1.0f / (1.0f + expf( diff));
    ((float2*)out)[b] = r;

    // ---- Reset counters for the next graph replay (last block to finish) ----
    __syncthreads();
    if (tid == 0) {
        __threadfence();
        const unsigned d = atomicAdd(&g_done, 1u);
        if (d == GRID - 1) {
            atomicExch(&g_ctr,  0u);
            atomicExch(&g_done, 0u);
        }
    }
}

extern "C" void kernel_launch(void* const* d_in, const int* in_sizes, int n_in,
                              void* d_out, int out_size) {
    const float* phi  = (const float*)d_in[0];   // (32768, 2, 10)
    const float* succ = (const float*)d_in[1];   // (128, 30, 30, 6)
    const float* w    = (const float*)d_in[2];   // (6,)
    float* out = (float*)d_out;                  // (32768, 2, 1)

    fused_kernel<<<GRID, THREADS>>>(phi, succ, w, out);
}

// round 4
// speedup vs baseline: 1.0425x; 1.0425x over previous
#include <cuda_runtime.h>
#include <math.h>

#define B_TOTAL 32768
#define X_DIM   30
#define Y_DIM   30
#define F_DIM   6
#define CELLS   (X_DIM * Y_DIM)      // 900
#define THREADS 256
#define PROD_BLOCKS 113               // 113 * 8 cells = 904 >= 900
#define CONS_BLOCKS 128               // 128 * 256 = 32768 batch elems
#define GRID (PROD_BLOCKS + CONS_BLOCKS)

__device__ float    g_S[CELLS];
__device__ unsigned g_ctr  = 0;   // producer-done counter (release/acquire)
__device__ unsigned g_done = 0;   // consumer completion counter (for reset)

__global__ void __launch_bounds__(THREADS)
fused_kernel(const float* __restrict__ phi,
             const float* __restrict__ succ,
             const float* __restrict__ w,
             float* __restrict__ out) {
    const int tid = threadIdx.x;
    const int bid = blockIdx.x;

    const float w0 = __ldg(&w[0]), w1 = __ldg(&w[1]), w2 = __ldg(&w[2]);
    const float w3 = __ldg(&w[3]), w4 = __ldg(&w[4]), w5 = __ldg(&w[5]);

    if (bid < PROD_BLOCKS) {
        // ================= PRODUCER: 8 cells per block =================
        // tid = h*128 + p ; h in {0,1} -> 4-cell group, p = policy index.
        const int h    = tid >> 7;
        const int p    = tid & 127;
        const int lane = tid & 31;
        const int w4g  = (tid >> 5) & 3;
        const int cell0 = bid * 8 + h * 4;
        const bool valid = cell0 < CELLS;

        __shared__ float smax[2][4][4];
        __shared__ float ssum[2][4][4][2];

        float v[4], x[4];
        if (valid) {
            // byte offset = p*21600 + cell0*24 (cell0 multiple of 4) -> 16B aligned
            const float4* base =
                (const float4*)(succ + (size_t)p * (CELLS * F_DIM) + (size_t)cell0 * F_DIM);
            const float4 q0 = base[0], q1 = base[1], q2 = base[2];
            const float4 q3 = base[3], q4 = base[4], q5 = base[5];

            v[0] = q0.x*w0 + q0.y*w1 + q0.z*w2 + q0.w*w3 + q1.x*w4 + q1.y*w5;
            v[1] = q1.z*w0 + q1.w*w1 + q2.x*w2 + q2.y*w3 + q2.z*w4 + q2.w*w5;
            v[2] = q3.x*w0 + q3.y*w1 + q3.z*w2 + q3.w*w3 + q4.x*w4 + q4.y*w5;
            v[3] = q4.z*w0 + q4.w*w1 + q5.x*w2 + q5.y*w3 + q5.z*w4 + q5.w*w5;

#pragma unroll
            for (int j = 0; j < 4; ++j) x[j] = v[j] / 0.001f;   // match vs / T

#pragma unroll
            for (int j = 0; j < 4; ++j) {
                float mm = x[j];
#pragma unroll
                for (int s = 16; s > 0; s >>= 1)
                    mm = fmaxf(mm, __shfl_xor_sync(0xFFFFFFFFu, mm, s));
                if (lane == 0) smax[h][j][w4g] = mm;
            }
        }
        __syncthreads();

        if (valid) {
#pragma unroll
            for (int j = 0; j < 4; ++j) {
                const float mx = fmaxf(fmaxf(smax[h][j][0], smax[h][j][1]),
                                       fmaxf(smax[h][j][2], smax[h][j][3]));
                float e  = __expf(x[j] - mx);
                float ev = e * v[j];
#pragma unroll
                for (int s = 16; s > 0; s >>= 1) {
                    e  += __shfl_xor_sync(0xFFFFFFFFu, e,  s);
                    ev += __shfl_xor_sync(0xFFFFFFFFu, ev, s);
                }
                if (lane == 0) { ssum[h][j][w4g][0] = e; ssum[h][j][w4g][1] = ev; }
            }
        }
        __syncthreads();

        if (valid && (tid & 127) < 4) {
            const int j = tid & 3;
            const float se  = ssum[h][j][0][0] + ssum[h][j][1][0]
                            + ssum[h][j][2][0] + ssum[h][j][3][0];
            const float sev = ssum[h][j][0][1] + ssum[h][j][1][1]
                            + ssum[h][j][2][1] + ssum[h][j][3][1];
            g_S[cell0 + j] = sev / se;
        }
        __syncthreads();   // block-scope ordering of g_S writes before the release
        if (tid == 0) {
            unsigned* ctr = &g_ctr;
            asm volatile("red.release.gpu.global.add.u32 [%0], 1;"
                         :: "l"(ctr) : "memory");
        }
    } else {
        // ================= CONSUMER: 256 batch elems per block =================
        const int b = (bid - PROD_BLOCKS) * THREADS + tid;

        // Issue DRAM loads immediately; their latency hides the producer wait.
        const float4* ph = (const float4*)(phi + (size_t)b * 20);
        const float4 a0 = ph[0];
        const float4 a1 = ph[1];
        const float4 a2 = ph[2];
        const float4 a3 = ph[3];
        const float4 a4 = ph[4];

        const float pr0 = a0.x*w0 + a0.y*w1 + a0.z*w2 + a0.w*w3 + a1.x*w4 + a1.y*w5;
        const float pr1 = a2.z*w0 + a2.w*w1 + a3.x*w2 + a3.y*w3 + a3.z*w4 + a3.w*w5;

        const int is0 = (int)a1.z * Y_DIM + (int)a1.w;
        const int ie0 = (int)a2.x * Y_DIM + (int)a2.y;
        const int is1 = (int)a4.x * Y_DIM + (int)a4.y;
        const int ie1 = (int)a4.z * Y_DIM + (int)a4.w;

        // Wait until all producers have released their S entries.
        if (tid == 0) {
            const unsigned* ctr = &g_ctr;
            unsigned vct;
            do {
                asm volatile("ld.acquire.gpu.global.u32 %0, [%1];"
                             : "=r"(vct) : "l"(ctr) : "memory");
                if (vct >= PROD_BLOCKS) break;
                __nanosleep(64);
            } while (true);
        }
        __syncthreads();

        const float d0 = pr0 + (__ldcg(&g_S[ie0]) - __ldcg(&g_S[is0]));
        const float d1 = pr1 + (__ldcg(&g_S[ie1]) - __ldcg(&g_S[is1]));

        const float diff = d0 - d1;
        float2 r;
        r.x = 1.0f / (1.0f + __expf(-diff));
        r.y = 1.0f / (1.0f + __expf( diff));
        ((float2*)out)[b] = r;

        // Reset counters for the next graph replay: last consumer block does it.
        __syncthreads();
        if (tid == 0) {
            const unsigned d = atomicAdd(&g_done, 1u);
            if (d == CONS_BLOCKS - 1) {
                atomicExch(&g_ctr,  0u);
                atomicExch(&g_done, 0u);
            }
        }
    }
}

extern "C" void kernel_launch(void* const* d_in, const int* in_sizes, int n_in,
                              void* d_out, int out_size) {
    const float* phi  = (const float*)d_in[0];   // (32768, 2, 10)
    const float* succ = (const float*)d_in[1];   // (128, 30, 30, 6)
    const float* w    = (const float*)d_in[2];   // (6,)
    float* out = (float*)d_out;                  // (32768, 2, 1)

    fused_kernel<<<GRID, THREADS>>>(phi, succ, w, out);
}